// round 10
// baseline (speedup 1.0000x reference)
#include <cuda_runtime.h>
#include <cstdint>

#define BB     256
#define TT     32
#define CNN    512
#define HWSQ   196      // 14*14
#define HID    8
#define NG     32       // 4*HID gates
#define VV     37
#define CHUNKS 8                // pooling CTAs per batch
#define CPB    (CNN/CHUNKS)     // 64 channels per CTA
#define PTHR   256
#define PWARP  (PTHR/32)        // 8
#define CPW    (CPB/PWARP)      // 8 channels per warp
#define UNR    4
#define TTHR   128

// xproj rows: [b][t][gate]; t=0 row holds the b_in @ W_ih^T bias row
__device__ float g_xproj[BB * TT * NG];
// xproj0 partials from fc_in chunks: [b][chunk][gate]
__device__ float g_xp0p[BB * CHUNKS * NG];

__device__ __forceinline__ unsigned long long mk_policy_evict_last() {
    unsigned long long p;
    asm("createpolicy.fractional.L2::evict_last.b64 %0, 1.0;" : "=l"(p));
    return p;
}

__device__ __forceinline__ float4 ldg_el(const float4* p, unsigned long long pol) {
    float4 v;
    asm volatile("ld.global.nc.L2::cache_hint.v4.f32 {%0,%1,%2,%3}, [%4], %5;"
                 : "=f"(v.x), "=f"(v.y), "=f"(v.z), "=f"(v.w)
                 : "l"(p), "l"(pol));
    return v;
}

__device__ __forceinline__ float tanh_fast(float x) {
    float y;
    asm("tanh.approx.f32 %0, %1;" : "=f"(y) : "f"(x));
    return y;
}
__device__ __forceinline__ float sigmoid_fast(float x) {
    return fmaf(0.5f, tanh_fast(0.5f * x), 0.5f);
}

// ---------------------------------------------------------------------------
// Kernel A: pooling + ALL batch-parallel prework, hidden under the BW stream.
// grid = 2048 (8 CTAs/batch). Each CTA:
//   - pools its 64 channels (evict_last, ~8 TB/s effective)
//   - fc_in partial dots p[c,v] over its channels (reads its W_in slice)
//   - projects p[c,.] through W_ih -> g_xp0p[b][c][gate]
//   - chunk 0 additionally: xproj rows for t>=1 from captions, t=0 bias row
// ---------------------------------------------------------------------------
__global__ __launch_bounds__(PTHR, 6) void pool_kernel(
    const float* __restrict__ feat,     // [B, 512, 14, 14]
    const float* __restrict__ captions, // [B, T, V]
    const float* __restrict__ W_in,     // [37, 512]
    const float* __restrict__ b_in,     // [37]
    const float* __restrict__ W_ih)     // [32, 37]
{
    __shared__ float spool[CPB];        // 64 channel means
    __shared__ float sp[VV];            // fc_in partial dots for this chunk
    __shared__ float sWih[NG * VV];

    const int b     = blockIdx.x >> 3;
    const int chunk = blockIdx.x & 7;
    const int warp  = threadIdx.x >> 5;
    const int lane  = threadIdx.x & 31;
    const int tid   = threadIdx.x;

    // stage W_ih (coalesced; covered by the post-pooling barrier)
    for (int i = tid; i < NG * VV; i += PTHR) sWih[i] = W_ih[i];

    const unsigned long long pol = mk_policy_evict_last();
    const float4* base = reinterpret_cast<const float4*>(feat + (size_t)b * CNN * HWSQ);
    const int c0 = chunk * CPB + warp * CPW;

    #pragma unroll
    for (int cc = 0; cc < CPW; cc += UNR) {
        float4 a[UNR], q[UNR];
        #pragma unroll
        for (int u = 0; u < UNR; ++u) {
            const float4* p = base + (size_t)(c0 + cc + u) * 49;   // 196 floats
            a[u] = ldg_el(p + lane, pol);
            if (lane < 17) q[u] = ldg_el(p + lane + 32, pol);
        }
        float s[UNR];
        #pragma unroll
        for (int u = 0; u < UNR; ++u) {
            s[u] = a[u].x + a[u].y + a[u].z + a[u].w;
            if (lane < 17) s[u] += q[u].x + q[u].y + q[u].z + q[u].w;
        }
        #pragma unroll
        for (int o = 16; o > 0; o >>= 1) {
            #pragma unroll
            for (int u = 0; u < UNR; ++u)
                s[u] += __shfl_down_sync(0xffffffffu, s[u], o);
        }
        if (lane == 0) {
            #pragma unroll
            for (int u = 0; u < UNR; ++u)
                spool[warp * CPW + cc + u] = s[u] * (1.0f / 196.0f);
        }
    }
    __syncthreads();

    // fc_in partials p[c,v] (no bias): warp w -> v = w, w+8, ...
    {
        const float p1 = spool[lane];
        const float p2 = spool[lane + 32];
        for (int v = warp; v < VV; v += PWARP) {
            const float* wr = W_in + v * CNN + chunk * CPB;
            float s = p1 * wr[lane] + p2 * wr[lane + 32];
            #pragma unroll
            for (int o = 16; o > 0; o >>= 1)
                s += __shfl_down_sync(0xffffffffu, s, o);
            if (lane == 0) sp[v] = s;
        }
    }
    __syncthreads();

    // xp0p[c][g] = sum_v p[c,v] * W_ih[g,v]; warp w -> gates g = w, w+8, ...
    {
        const float pv1 = (lane < VV) ? sp[lane] : 0.0f;           // lane 0..31
        const float pv2 = (lane < VV - 32) ? sp[32 + lane] : 0.0f; // lane 0..4
        #pragma unroll
        for (int i = 0; i < 4; ++i) {
            int g = warp + i * PWARP;
            float s = pv1 * sWih[g * VV + lane];
            if (lane < VV - 32) s += pv2 * sWih[g * VV + 32 + lane];
            #pragma unroll
            for (int o = 16; o > 0; o >>= 1)
                s += __shfl_down_sync(0xffffffffu, s, o);
            if (lane == 0) g_xp0p[(b * CHUNKS + chunk) * NG + g] = s;
        }
    }

    // chunk 0: xproj rows. t=0 -> x = b_in (bias row); t>=1 -> x = captions[t-1]
    if (chunk == 0) {
        for (int t = warp; t < TT; t += PWARP) {
            const float* x = (t == 0) ? b_in
                                      : (captions + ((size_t)b * TT + (t - 1)) * VV);
            float xv1 = x[lane];                                   // lane 0..31
            float xv2 = (lane < VV - 32) ? x[32 + lane] : 0.0f;
            float acc = 0.0f;
            const float* wrow = &sWih[lane * VV];                  // gate = lane
            #pragma unroll
            for (int k = 0; k < 32; ++k)
                acc = fmaf(__shfl_sync(0xffffffffu, xv1, k), wrow[k], acc);
            #pragma unroll
            for (int k = 0; k < VV - 32; ++k)
                acc = fmaf(__shfl_sync(0xffffffffu, xv2, k), wrow[32 + k], acc);
            g_xproj[(b * TT + t) * NG + lane] = acc;
        }
    }
}

// ---------------------------------------------------------------------------
// Kernel B: slim tail. grid = 256, block = 128.
// stage -> xproj0 8-term sum -> warp-0 recurrence -> fc_out -> time-softmax.
// ---------------------------------------------------------------------------
__global__ __launch_bounds__(TTHR) void tail_kernel(
    const float* __restrict__ b_ih,     // [32]
    const float* __restrict__ W_hh,     // [32, 8]
    const float* __restrict__ b_hh,     // [32]
    const float* __restrict__ W_out,    // [37, 8]
    const float* __restrict__ b_out,    // [37]
    float* __restrict__ out)            // [B, T, V]
{
    __shared__ float sxproj[TT * NG];   // [t][gate]
    __shared__ float sxp0p[CHUNKS * NG];
    __shared__ float sWhh[NG * 9];      // padded stride 9
    __shared__ float sWout[VV * 9];     // padded stride 9
    __shared__ float sb[NG];
    __shared__ float sbo[VV];
    __shared__ float hbuf[TT * HID];
    __shared__ float logits[TT * VV];

    const int b    = blockIdx.x;
    const int tid  = threadIdx.x;
    const int warp = tid >> 5;
    const int lane = tid & 31;

    // ---- one batched, coalesced staging exposure ----
    for (int i = tid; i < TT * NG; i += TTHR)
        sxproj[i] = g_xproj[b * TT * NG + i];
    for (int i = tid; i < CHUNKS * NG; i += TTHR)
        sxp0p[i] = g_xp0p[b * CHUNKS * NG + i];
    for (int i = tid; i < NG * HID; i += TTHR)
        sWhh[(i >> 3) * 9 + (i & 7)] = W_hh[i];
    for (int i = tid; i < VV * HID; i += TTHR)
        sWout[(i / 8) * 9 + (i & 7)] = W_out[i];
    if (tid < NG) sb[tid]  = b_ih[tid] + b_hh[tid];
    if (tid < VV) sbo[tid] = b_out[tid];
    __syncthreads();

    // ---- xproj0 = bias row + 8 chunk partials (fixed order) ----
    if (tid < NG) {
        float a = sxproj[tid];
        #pragma unroll
        for (int c = 0; c < CHUNKS; ++c)
            a += sxp0p[c * NG + tid];
        sxproj[tid] = a;
    }
    __syncthreads();

    // ---- recurrence (warp 0): lane = gate, unit j8 = lane & 7 ----
    if (warp == 0) {
        const float sbreg = sb[lane];
        float whh0 = sWhh[lane * 9 + 0], whh1 = sWhh[lane * 9 + 1];
        float whh2 = sWhh[lane * 9 + 2], whh3 = sWhh[lane * 9 + 3];
        float whh4 = sWhh[lane * 9 + 4], whh5 = sWhh[lane * 9 + 5];
        float whh6 = sWhh[lane * 9 + 6], whh7 = sWhh[lane * 9 + 7];

        float h0 = 0.f, h1 = 0.f, h2 = 0.f, h3 = 0.f;
        float h4 = 0.f, h5 = 0.f, h6 = 0.f, h7 = 0.f;
        float c = 0.f;
        const int j8 = lane & 7;

        #pragma unroll
        for (int t = 0; t < TT; ++t) {
            float ga = sxproj[t * NG + lane] + sbreg;
            float gb = 0.0f;
            ga = fmaf(h0, whh0, ga);  gb = fmaf(h1, whh1, gb);
            ga = fmaf(h2, whh2, ga);  gb = fmaf(h3, whh3, gb);
            ga = fmaf(h4, whh4, ga);  gb = fmaf(h5, whh5, gb);
            ga = fmaf(h6, whh6, ga);  gb = fmaf(h7, whh7, gb);
            float gate = ga + gb;

            float gi = __shfl_sync(0xffffffffu, gate, j8);
            float gf = __shfl_sync(0xffffffffu, gate, j8 + 8);
            float gg = __shfl_sync(0xffffffffu, gate, j8 + 16);
            float go = __shfl_sync(0xffffffffu, gate, j8 + 24);

            float i_ = sigmoid_fast(gi);
            float f_ = sigmoid_fast(gf);
            float g_ = tanh_fast(gg);
            float o_ = sigmoid_fast(go);
            c = fmaf(f_, c, i_ * g_);
            float hn = o_ * tanh_fast(c);

            h0 = __shfl_sync(0xffffffffu, hn, 0);
            h1 = __shfl_sync(0xffffffffu, hn, 1);
            h2 = __shfl_sync(0xffffffffu, hn, 2);
            h3 = __shfl_sync(0xffffffffu, hn, 3);
            h4 = __shfl_sync(0xffffffffu, hn, 4);
            h5 = __shfl_sync(0xffffffffu, hn, 5);
            h6 = __shfl_sync(0xffffffffu, hn, 6);
            h7 = __shfl_sync(0xffffffffu, hn, 7);

            if (lane < HID) hbuf[t * HID + lane] = hn;
        }
    }
    __syncthreads();

    // ---- fc_out: warp w handles t = w, w+4, ... (all smem) ----
    for (int t = warp; t < TT; t += 4) {
        float acc1 = sbo[lane];
        float acc2 = (lane < VV - 32) ? sbo[32 + lane] : 0.0f;
        #pragma unroll
        for (int j = 0; j < HID; ++j) {
            float hv = hbuf[t * HID + j];
            acc1 = fmaf(hv, sWout[lane * 9 + j], acc1);
            if (lane < VV - 32)
                acc2 = fmaf(hv, sWout[(32 + lane) * 9 + j], acc2);
        }
        logits[t * VV + lane] = acc1;
        if (lane < VV - 32) logits[t * VV + 32 + lane] = acc2;
    }
    __syncthreads();

    // ---- softmax over TIME axis (thread v owns column v) ----
    if (tid < VV) {
        float m = -1e30f;
        #pragma unroll
        for (int t = 0; t < TT; ++t)
            m = fmaxf(m, logits[t * VV + tid]);
        float s = 0.0f;
        #pragma unroll
        for (int t = 0; t < TT; ++t) {
            float e = __expf(logits[t * VV + tid] - m);
            s += e;
            logits[t * VV + tid] = e;
        }
        float r = 1.0f / s;
        #pragma unroll
        for (int t = 0; t < TT; ++t)
            logits[t * VV + tid] *= r;
    }
    __syncthreads();

    // ---- coalesced store ----
    float* ob = out + (size_t)b * TT * VV;
    for (int i = tid; i < TT * VV; i += TTHR)
        ob[i] = logits[i];
}

// ---------------------------------------------------------------------------
extern "C" void kernel_launch(void* const* d_in, const int* in_sizes, int n_in,
                              void* d_out, int out_size)
{
    const float* features = (const float*)d_in[0];
    const float* captions = (const float*)d_in[1];
    const float* W_ih     = (const float*)d_in[2];
    const float* b_ih     = (const float*)d_in[3];
    const float* W_hh     = (const float*)d_in[4];
    const float* b_hh     = (const float*)d_in[5];
    const float* W_in     = (const float*)d_in[6];
    const float* b_in     = (const float*)d_in[7];
    const float* W_out    = (const float*)d_in[8];
    const float* b_out    = (const float*)d_in[9];
    float* out = (float*)d_out;

    pool_kernel<<<BB * CHUNKS, PTHR>>>(features, captions, W_in, b_in, W_ih);
    tail_kernel<<<BB, TTHR>>>(b_ih, W_hh, b_hh, W_out, b_out, out);
    (void)in_sizes; (void)n_in; (void)out_size;
}